// round 7
// baseline (speedup 1.0000x reference)
#include <cuda_runtime.h>
#include <cuda_fp16.h>
#include <cstdint>
#include <cstddef>

// ---------------- problem dims (fixed) ----------------
#define DIMD 1024
#define HID  4096
#define MTOK 16384
#define NCH_A1 16        // GEMM1 K chunks: 8 hi + 8 lo (128 int8 each)
#define NCH_R  64        // GEMM2 K chunks: 32 hi + 32 lo
#define TILEB 16384      // one 128x128 int8 tile, SW128-swizzled

// ---------------- device scratch ----------------
__device__ __align__(1024) signed char g_A1i[(size_t)(MTOK/128)*NCH_A1*TILEB];
__device__ __align__(1024) signed char g_B1i[(size_t)(HID /128)*NCH_A1*TILEB];
__device__ __align__(1024) signed char g_Ri [(size_t)(MTOK/128)*NCH_R *TILEB];
__device__ __align__(1024) signed char g_B2i[(size_t)(DIMD/128)*NCH_R *TILEB];
__device__ __align__(256)  __half g_Rh[(size_t)MTOK*HID];   // rr fp16 row-major
__device__ float g_scale_fc[HID];
__device__ float g_scale_pj[DIMD];
__device__ float g_W[16*DIMD];          // fast_b @ v
__device__ float g_T2[(size_t)MTOK*16]; // adapter activations
__device__ float g_Ug[(size_t)HID*16];  // gate * u
__device__ float g_sx[MTOK];            // x row scales
__device__ float g_s2[MTOK];            // rr row scales

// ---------------- helpers ----------------
__device__ __forceinline__ uint32_t smem_to_u32(const void* p) {
    uint32_t a;
    asm("{ .reg .u64 t; cvta.to.shared.u64 t, %1; cvt.u32.u64 %0, t; }" : "=r"(a) : "l"(p));
    return a;
}
#define SW128(o) ((o) ^ (((o) >> 3) & 0x70))

#define MBARRIER_INIT(mbar, count) \
    asm volatile("mbarrier.init.shared.b64 [%0], %1;" :: "r"((uint32_t)(mbar)), "r"((uint32_t)(count)) : "memory")
#define MBARRIER_EXPECT_TX(mbar, tx) \
    asm volatile("mbarrier.arrive.expect_tx.shared.b64 _, [%0], %1;" :: "r"((uint32_t)(mbar)), "r"((uint32_t)(tx)) : "memory")
#define MBARRIER_ARRIVE(mbar) \
    asm volatile("mbarrier.arrive.shared.b64 _, [%0];" :: "r"((uint32_t)(mbar)) : "memory")

#define MBARRIER_WAIT_PARITY(mbar, par) do { \
    uint32_t _m = (uint32_t)(mbar); uint32_t _p = (uint32_t)(par); uint32_t _d; \
    asm volatile("{\n\t.reg .pred p;\n\t" \
        "mbarrier.try_wait.parity.acquire.cta.shared::cta.b64 p, [%1], %2;\n\t" \
        "selp.b32 %0, 1, 0, p;\n\t}" : "=r"(_d) : "r"(_m), "r"(_p) : "memory"); \
    if (!_d) { \
        asm volatile("{\n\t.reg .pred P1;\n\t" \
            "WL_%=:\n\t" \
            "mbarrier.try_wait.parity.acquire.cta.shared::cta.b64 P1, [%0], %1, 0x989680;\n\t" \
            "@P1 bra.uni WD_%=;\n\tbra.uni WL_%=;\n\tWD_%=:\n\t}" \
            :: "r"(_m), "r"(_p) : "memory"); \
    } \
} while (0)

__device__ __forceinline__ void bulk_g2s(uint32_t dst, const void* src, uint32_t bytes, uint32_t mbar) {
    asm volatile("cp.async.bulk.shared::cluster.global.mbarrier::complete_tx::bytes [%0], [%1], %2, [%3];"
        :: "r"(dst), "l"(src), "r"(bytes), "r"(mbar) : "memory");
}

__device__ __forceinline__ void ldm_x4(uint32_t addr, uint32_t* r) {
    asm volatile("ldmatrix.sync.aligned.m8n8.x4.shared.b16 {%0,%1,%2,%3}, [%4];"
        : "=r"(r[0]), "=r"(r[1]), "=r"(r[2]), "=r"(r[3]) : "r"(addr));
}
// int8 IMMA, K=32 per instruction, exact int32 accumulation
__device__ __forceinline__ void mma_s8(int32_t* c, const uint32_t* a, uint32_t b0, uint32_t b1) {
    asm volatile("mma.sync.aligned.m16n8k32.row.col.s32.s8.s8.s32 "
        "{%0,%1,%2,%3}, {%4,%5,%6,%7}, {%8,%9}, {%0,%1,%2,%3};"
        : "+r"(c[0]), "+r"(c[1]), "+r"(c[2]), "+r"(c[3])
        : "r"(a[0]), "r"(a[1]), "r"(a[2]), "r"(a[3]), "r"(b0), "r"(b1));
}

// ============================================================================
// prep kernels
// ============================================================================

// per-output-row abs-mean scale -> ternary int8, duplicated hi|lo chunk groups.
// For w_fc also emits g_Ug = gate*u.
__global__ void pack_w_kernel(const float* __restrict__ w, int K, int nch,
                              signed char* __restrict__ Bq,
                              float* __restrict__ scaleOut,
                              const float* __restrict__ u,
                              const float* __restrict__ gatep)
{
    int i = blockIdx.x;
    int t = threadIdx.x;  // 128
    const float* wr = w + (size_t)i * K;
    double s = 0.0;
    for (int j = t; j < K; j += 128) s += fabs((double)wr[j]);
    for (int o = 16; o; o >>= 1) s += __shfl_down_sync(0xffffffffu, s, o);
    __shared__ double red[4];
    __shared__ float scsh;
    if ((t & 31) == 0) red[t >> 5] = s;
    __syncthreads();
    if (t == 0) {
        float m = (float)((red[0] + red[1] + red[2] + red[3]) / K);
        scsh = fmaxf(m, 1e-5f);
        scaleOut[i] = scsh;
    }
    __syncthreads();
    float scale = scsh;
    int tile = i >> 7, row = i & 127, halfch = nch >> 1;
    for (int j = t; j < K; j += 128) {
        float tern = rintf(wr[j] / scale);
        tern = fminf(fmaxf(tern, -1.f), 1.f);
        signed char tv = (signed char)tern;
        int ch = j >> 7, cb = j & 127;
        uint32_t sw = SW128((uint32_t)(row * 128 + cb));
        Bq[(size_t)(tile * nch + ch) * TILEB + sw] = tv;
        Bq[(size_t)(tile * nch + ch + halfch) * TILEB + sw] = tv;
    }
    if (u != nullptr && t < 16)
        g_Ug[(size_t)i * 16 + t] = (*gatep) * u[(size_t)i * 16 + t];
}

// W = fast_b @ v  (16 x 1024)
__global__ void compose_w_kernel(const float* __restrict__ fb, const float* __restrict__ v)
{
    int idx = blockIdx.x * blockDim.x + threadIdx.x;
    if (idx >= 16 * DIMD) return;
    int j = idx >> 10, d = idx & 1023;
    float s = 0.f;
#pragma unroll
    for (int r = 0; r < 16; r++) s += fb[j * 16 + r] * v[r * DIMD + d];
    g_W[idx] = s;
}

// per-token: row scale, hi/lo int8 quantize into chunk-major A1, adapter t2
__global__ void prep_x_kernel(const float* __restrict__ x)
{
    __shared__ float xs[1024];
    __shared__ float red[4];
    __shared__ float s_sh;
    int m = blockIdx.x;
    int tid = threadIdx.x;  // 128
    const float* xr = x + (size_t)m * DIMD;
    float mx = 0.f;
    for (int i = tid; i < 1024; i += 128) {
        float v = xr[i];
        xs[i] = v;
        mx = fmaxf(mx, fabsf(v));
    }
#pragma unroll
    for (int o = 16; o; o >>= 1) mx = fmaxf(mx, __shfl_down_sync(0xffffffffu, mx, o));
    if ((tid & 31) == 0) red[tid >> 5] = mx;
    __syncthreads();
    if (tid == 0) {
        float v = fmaxf(fmaxf(red[0], red[1]), fmaxf(red[2], red[3]));
        s_sh = (v > 0.f) ? v / 127.f : 1.f;
        g_sx[m] = s_sh;
    }
    __syncthreads();
    float inv = 1.f / s_sh;
    int tile = m >> 7, row = m & 127;
    int col0 = tid * 8;
    int ch = col0 >> 7, cb = col0 & 127;
    signed char hq[8], lq[8];
#pragma unroll
    for (int i = 0; i < 8; i++) {
        float q = xs[col0 + i] * inv;
        float qh = rintf(q);
        qh = fminf(fmaxf(qh, -127.f), 127.f);
        float ql = rintf((q - qh) * 252.f);
        hq[i] = (signed char)qh;
        lq[i] = (signed char)ql;
    }
    uint32_t sw0 = SW128((uint32_t)(row * 128 + cb));
    size_t offh = (size_t)(tile * NCH_A1 + ch) * TILEB;
    size_t offl = (size_t)(tile * NCH_A1 + ch + 8) * TILEB;
    *(uint32_t*)(g_A1i + offh + sw0)     = *(uint32_t*)&hq[0];
    *(uint32_t*)(g_A1i + offh + sw0 + 4) = *(uint32_t*)&hq[4];
    *(uint32_t*)(g_A1i + offl + sw0)     = *(uint32_t*)&lq[0];
    *(uint32_t*)(g_A1i + offl + sw0 + 4) = *(uint32_t*)&lq[4];
    // adapter t2 (f32, exact)
    int j = tid >> 3, p = tid & 7;
    const float* wr = g_W + j * 1024 + p * 128;
    const float* xp = xs + p * 128;
    float s = 0.f;
#pragma unroll 8
    for (int i = 0; i < 128; i++) s += xp[i] * wr[i];
#pragma unroll
    for (int o = 4; o; o >>= 1) s += __shfl_down_sync(0xffffffffu, s, o);
    if (p == 0) g_T2[(size_t)m * 16 + j] = s;
}

// rr fp16 row -> per-row scale + hi/lo int8 chunk-major for GEMM2
__global__ void quantize_rr_kernel()
{
    __shared__ __half rs[4096];
    __shared__ float red[8];
    __shared__ float s_sh;
    int m = blockIdx.x;
    int tid = threadIdx.x;  // 256
    const __half* rr = g_Rh + (size_t)m * HID;
#pragma unroll
    for (int i = 0; i < 2; i++) {
        int o = (tid + i * 256) * 8;
        *(uint4*)(rs + o) = *(const uint4*)(rr + o);
    }
    __syncthreads();
    float mx = 0.f;
    for (int i = tid; i < 4096; i += 256) mx = fmaxf(mx, __half2float(rs[i]));
#pragma unroll
    for (int o = 16; o; o >>= 1) mx = fmaxf(mx, __shfl_down_sync(0xffffffffu, mx, o));
    if ((tid & 31) == 0) red[tid >> 5] = mx;
    __syncthreads();
    if (tid == 0) {
        float v = 0.f;
#pragma unroll
        for (int i = 0; i < 8; i++) v = fmaxf(v, red[i]);
        s_sh = (v > 0.f) ? v / 127.f : 1.f;
        g_s2[m] = s_sh;
    }
    __syncthreads();
    float inv = 1.f / s_sh;
    int tile = m >> 7, row = m & 127;
    int c0 = tid * 16;
    int ch = c0 >> 7, cb = c0 & 127;
    size_t oh = (size_t)(tile * NCH_R + ch) * TILEB + SW128((uint32_t)(row * 128 + cb));
    size_t ol = (size_t)(tile * NCH_R + ch + 32) * TILEB + SW128((uint32_t)(row * 128 + cb));
#pragma unroll
    for (int q4 = 0; q4 < 4; q4++) {
        signed char hb[4], lb[4];
#pragma unroll
        for (int i = 0; i < 4; i++) {
            float v = __half2float(rs[c0 + q4 * 4 + i]) * inv;
            float qh = rintf(v);
            float ql = rintf((v - qh) * 252.f);
            hb[i] = (signed char)qh;
            lb[i] = (signed char)ql;
        }
        *(uint32_t*)(g_Ri + oh + q4 * 4) = *(uint32_t*)hb;
        *(uint32_t*)(g_Ri + ol + q4 * 4) = *(uint32_t*)lb;
    }
}

// ============================================================================
// int8 GEMM: C[128,128] tile; chunks of K=128 int8; two int32 acc banks
// (hi chunks -> acc0, lo chunks -> acc1); cp.async.bulk + mbarrier ring.
// EPI==1: h = sx_m*sfc_n*(acc0+acc1/252) + adapter; rr=relu(h)^2 -> g_Rh fp16
// EPI==2: out = s2_m*spj_n*(acc0+acc1/252) (f32)
// ============================================================================
#define NSTAGE 6
#define STAGEB 32768            // A 16KB + B 16KB
#define GEMM_SMEM (NSTAGE * STAGEB)

template <int EPI>
__global__ void __launch_bounds__(256, 1)
gemm_i8_kernel(const signed char* __restrict__ A, const signed char* __restrict__ B,
               const float* __restrict__ rowsc, const float* __restrict__ colsc,
               float* __restrict__ out, int kChunks, int nTiles)
{
    extern __shared__ char smem_raw[];
    __shared__ __align__(8) uint64_t mbar_store[2 * NSTAGE];
    __shared__ float s_cs[128];
    __shared__ float s_rs[128];
    __shared__ float t2s[(EPI == 1) ? 128 : 1][17];
    __shared__ float ugs[(EPI == 1) ? 128 : 1][17];
    const uint32_t DATA = smem_to_u32(smem_raw);
    const uint32_t FULL = smem_to_u32(mbar_store);
    const uint32_t EMPTY = FULL + 8 * NSTAGE;
    const int tid = (int)threadIdx.x;
    const int lane = tid & 31;
    const int wid = tid >> 5;
    const int wm = wid >> 2;
    const int wn = wid & 3;
    const int tile_m = (int)blockIdx.x / nTiles;
    const int tile_n = (int)blockIdx.x % nTiles;
    const int kHalf = kChunks >> 1;

    if (tid == 0) {
#pragma unroll
        for (int s = 0; s < NSTAGE; s++) {
            MBARRIER_INIT(FULL + 8 * s, 1);
            MBARRIER_INIT(EMPTY + 8 * s, 256);
        }
    }
    __syncthreads();

    const char* Ab = (const char*)A + (size_t)tile_m * kChunks * TILEB;
    const char* Bb = (const char*)B + (size_t)tile_n * kChunks * TILEB;

    auto produce = [&](int j) {
        int s = j % NSTAGE;
        uint32_t dst = DATA + s * STAGEB;
        MBARRIER_EXPECT_TX(FULL + 8 * s, 2 * TILEB);
        bulk_g2s(dst,         Ab + (size_t)j * TILEB, TILEB, FULL + 8 * s);
        bulk_g2s(dst + TILEB, Bb + (size_t)j * TILEB, TILEB, FULL + 8 * s);
    };

    if (tid == 0) {
        int npre = kChunks < NSTAGE ? kChunks : NSTAGE;
        for (int j = 0; j < npre; j++) produce(j);
    }

    int32_t acc0[16][4], acc1[16][4];
#pragma unroll
    for (int i = 0; i < 16; i++)
#pragma unroll
        for (int q = 0; q < 4; q++) { acc0[i][q] = 0; acc1[i][q] = 0; }

    const int lr = lane & 15, lc = lane >> 4;
    uint32_t afr[4][4], bfr[2][4];

    auto do_chunk = [&](uint32_t sA, uint32_t sB, int32_t (&acc)[16][4]) {
#pragma unroll
        for (int ks = 0; ks < 4; ks++) {
            uint32_t bcol = (uint32_t)(ks * 32 + lc * 16);
#pragma unroll
            for (int im = 0; im < 4; im++) {
                int row = wm * 64 + im * 16 + lr;
                ldm_x4(sA + SW128((uint32_t)row * 128 + bcol), afr[im]);
            }
#pragma unroll
            for (int in2 = 0; in2 < 2; in2++) {
                int row = wn * 32 + in2 * 16 + lr;
                ldm_x4(sB + SW128((uint32_t)row * 128 + bcol), bfr[in2]);
            }
#pragma unroll
            for (int im = 0; im < 4; im++)
#pragma unroll
                for (int g = 0; g < 4; g++)
                    mma_s8(acc[im * 4 + g], afr[im],
                           bfr[g >> 1][g & 1], bfr[g >> 1][(g & 1) + 2]);
        }
    };

    for (int k = 0; k < kChunks; k++) {
        int s = k % NSTAGE;
        int ph = (k / NSTAGE) & 1;
        MBARRIER_WAIT_PARITY(FULL + 8 * s, ph);
        uint32_t sA = DATA + s * STAGEB;
        uint32_t sB = sA + TILEB;
        if (k < kHalf) do_chunk(sA, sB, acc0);
        else           do_chunk(sA, sB, acc1);
        MBARRIER_ARRIVE(EMPTY + 8 * s);
        if (tid == 0) {
            int j = k + NSTAGE;
            if (j < kChunks) {
                MBARRIER_WAIT_PARITY(EMPTY + 8 * s, ph);
                produce(j);
            }
        }
    }

    // ---- epilogue ----
    if (tid < 128) {
        s_cs[tid] = colsc[tile_n * 128 + tid];
        s_rs[tid] = rowsc[tile_m * 128 + tid];
    }
    if (EPI == 1) {
        for (int i = tid; i < 2048; i += 256) {
            t2s[i >> 4][i & 15] = g_T2[((size_t)tile_m * 128 + (i >> 4)) * 16 + (i & 15)];
            ugs[i >> 4][i & 15] = g_Ug[((size_t)tile_n * 128 + (i >> 4)) * 16 + (i & 15)];
        }
    }
    __syncthreads();

    const float LOW = 1.f / 252.f;
#pragma unroll
    for (int im = 0; im < 4; im++) {
#pragma unroll
        for (int g = 0; g < 4; g++) {
            int i = im * 4 + g;
            int ncol = wn * 32 + g * 8 + (lane & 3) * 2;
            int lrow0 = wm * 64 + im * 16 + (lane >> 2);
#pragma unroll
            for (int half = 0; half < 2; half++) {
                int lrow = lrow0 + half * 8;
                float v0 = (float)acc0[i][half * 2 + 0] + (float)acc1[i][half * 2 + 0] * LOW;
                float v1 = (float)acc0[i][half * 2 + 1] + (float)acc1[i][half * 2 + 1] * LOW;
                float rsc = s_rs[lrow];
                float h0 = rsc * s_cs[ncol] * v0;
                float h1 = rsc * s_cs[ncol + 1] * v1;
                if (EPI == 1) {
                    float d0 = 0.f, d1 = 0.f;
#pragma unroll
                    for (int j = 0; j < 16; j++) {
                        float t = t2s[lrow][j];
                        d0 += t * ugs[ncol][j];
                        d1 += t * ugs[ncol + 1][j];
                    }
                    h0 += d0; h1 += d1;
                    float r0 = fmaxf(h0, 0.f), r1 = fmaxf(h1, 0.f);
                    __half2 hp;
                    hp.x = __float2half(r0 * r0);
                    hp.y = __float2half(r1 * r1);
                    *(__half2*)(g_Rh + ((size_t)(tile_m * 128 + lrow)) * HID + tile_n * 128 + ncol) = hp;
                } else {
                    float2 v;
                    v.x = h0; v.y = h1;
                    *(float2*)(out + ((size_t)(tile_m * 128 + lrow)) * DIMD + tile_n * 128 + ncol) = v;
                }
            }
        }
    }
}

// ============================================================================
// launch
// ============================================================================
extern "C" void kernel_launch(void* const* d_in, const int* in_sizes, int n_in,
                              void* d_out, int out_size)
{
    const float* x      = (const float*)d_in[0];
    const float* fast_b = (const float*)d_in[1];
    const float* w_fc   = (const float*)d_in[2];
    const float* w_proj = (const float*)d_in[3];
    const float* u      = (const float*)d_in[4];
    const float* v      = (const float*)d_in[5];
    const float* gate   = (const float*)d_in[6];

    void *pA1, *pB1, *pR, *pB2, *pSfc, *pSpj, *pSx, *pS2;
    cudaGetSymbolAddress(&pA1, g_A1i);
    cudaGetSymbolAddress(&pB1, g_B1i);
    cudaGetSymbolAddress(&pR,  g_Ri);
    cudaGetSymbolAddress(&pB2, g_B2i);
    cudaGetSymbolAddress(&pSfc, g_scale_fc);
    cudaGetSymbolAddress(&pSpj, g_scale_pj);
    cudaGetSymbolAddress(&pSx, g_sx);
    cudaGetSymbolAddress(&pS2, g_s2);

    cudaFuncSetAttribute(gemm_i8_kernel<1>, cudaFuncAttributeMaxDynamicSharedMemorySize, GEMM_SMEM);
    cudaFuncSetAttribute(gemm_i8_kernel<2>, cudaFuncAttributeMaxDynamicSharedMemorySize, GEMM_SMEM);

    // prep
    pack_w_kernel<<<HID, 128>>>(w_fc, DIMD, NCH_A1, (signed char*)pB1, (float*)pSfc, u, gate);
    pack_w_kernel<<<DIMD, 128>>>(w_proj, HID, NCH_R, (signed char*)pB2, (float*)pSpj, nullptr, nullptr);
    compose_w_kernel<<<(16 * DIMD + 255) / 256, 256>>>(fast_b, v);
    prep_x_kernel<<<MTOK, 128>>>(x);

    // GEMM1: h = x@(w_fc*s)^T + adapter; rr=relu(h)^2 -> g_Rh fp16
    gemm_i8_kernel<1><<<(MTOK / 128) * (HID / 128), 256, GEMM_SMEM>>>(
        (const signed char*)pA1, (const signed char*)pB1,
        (const float*)pSx, (const float*)pSfc, nullptr, NCH_A1, HID / 128);

    // quantize rr -> int8 hi/lo chunk-major
    quantize_rr_kernel<<<MTOK, 256>>>();

    // GEMM2: out = rr@(w_proj*s)^T (f32)
    gemm_i8_kernel<2><<<(MTOK / 128) * (DIMD / 128), 256, GEMM_SMEM>>>(
        (const signed char*)pR, (const signed char*)pB2,
        (const float*)pS2, (const float*)pSpj, (float*)d_out, NCH_R, DIMD / 128);
}

// round 9
// speedup vs baseline: 2.7539x; 2.7539x over previous
#include <cuda_runtime.h>
#include <cuda_fp16.h>
#include <cstdint>
#include <cstddef>

// ---------------- problem dims (fixed for this problem) ----------------
#define DIMD 1024
#define HID  4096
#define MTOK 16384            // 4*4096 tokens
#define KC1  17               // GEMM1 k-chunks of 64: 1024 + (16 adapter + 48 pad)
#define KC2  64               // GEMM2 k-chunks of 64: 4096
#define TILEB 16384           // one 128x64 fp16 tile, SW128-swizzled

// Chunk-major tile layouts: buf[tileIdx][kchunk][128 rows][128B swizzled row]
// ---------------- device scratch (no cudaMalloc allowed) ----------------
__device__ __align__(1024) __half g_A1[(size_t)(MTOK / 128) * KC1 * TILEB / 2];
__device__ __align__(1024) __half g_B1[(size_t)(HID  / 128) * KC1 * TILEB / 2];
__device__ __align__(1024) __half g_R [(size_t)(MTOK / 128) * KC2 * TILEB / 2];
__device__ __align__(1024) __half g_B2[(size_t)(DIMD / 128) * KC2 * TILEB / 2];
__device__ float g_scale_fc[HID];
__device__ float g_scale_pj[DIMD];
__device__ float g_W[16 * DIMD];   // fast_b @ v

// ---------------- helpers ----------------
__device__ __forceinline__ uint32_t smem_to_u32(const void* p) {
    uint32_t a;
    asm("{ .reg .u64 t; cvta.to.shared.u64 t, %1; cvt.u32.u64 %0, t; }" : "=r"(a) : "l"(p));
    return a;
}
#define SW128(o) ((o) ^ (((o) >> 3) & 0x70))

#define MBARRIER_INIT(mbar, count) \
    asm volatile("mbarrier.init.shared.b64 [%0], %1;" :: "r"((uint32_t)(mbar)), "r"((uint32_t)(count)) : "memory")
#define MBARRIER_EXPECT_TX(mbar, tx) \
    asm volatile("mbarrier.arrive.expect_tx.shared.b64 _, [%0], %1;" :: "r"((uint32_t)(mbar)), "r"((uint32_t)(tx)) : "memory")
#define MBARRIER_ARRIVE(mbar) \
    asm volatile("mbarrier.arrive.shared.b64 _, [%0];" :: "r"((uint32_t)(mbar)) : "memory")

#define MBARRIER_WAIT_PARITY(mbar, par) do { \
    uint32_t _m = (uint32_t)(mbar); uint32_t _p = (uint32_t)(par); uint32_t _d; \
    asm volatile("{\n\t.reg .pred p;\n\t" \
        "mbarrier.try_wait.parity.acquire.cta.shared::cta.b64 p, [%1], %2;\n\t" \
        "selp.b32 %0, 1, 0, p;\n\t}" : "=r"(_d) : "r"(_m), "r"(_p) : "memory"); \
    if (!_d) { \
        asm volatile("{\n\t.reg .pred P1;\n\t" \
            "WL_%=:\n\t" \
            "mbarrier.try_wait.parity.acquire.cta.shared::cta.b64 P1, [%0], %1, 0x989680;\n\t" \
            "@P1 bra.uni WD_%=;\n\tbra.uni WL_%=;\n\tWD_%=:\n\t}" \
            :: "r"(_m), "r"(_p) : "memory"); \
    } \
} while (0)

// bulk async copy GMEM -> SMEM with mbarrier complete_tx (base sm_90 ISA)
__device__ __forceinline__ void bulk_g2s(uint32_t dst, const void* src, uint32_t bytes, uint32_t mbar) {
    asm volatile("cp.async.bulk.shared::cluster.global.mbarrier::complete_tx::bytes [%0], [%1], %2, [%3];"
        :: "r"(dst), "l"(src), "r"(bytes), "r"(mbar) : "memory");
}

__device__ __forceinline__ void ldm_x4(uint32_t addr, uint32_t* r) {
    asm volatile("ldmatrix.sync.aligned.m8n8.x4.shared.b16 {%0,%1,%2,%3}, [%4];"
        : "=r"(r[0]), "=r"(r[1]), "=r"(r[2]), "=r"(r[3]) : "r"(addr));
}
__device__ __forceinline__ void mma16816(float* c, const uint32_t* a, uint32_t b0, uint32_t b1) {
    asm volatile("mma.sync.aligned.m16n8k16.row.col.f32.f16.f16.f32 "
        "{%0,%1,%2,%3}, {%4,%5,%6,%7}, {%8,%9}, {%0,%1,%2,%3};"
        : "+f"(c[0]), "+f"(c[1]), "+f"(c[2]), "+f"(c[3])
        : "r"(a[0]), "r"(a[1]), "r"(a[2]), "r"(a[3]), "r"(b0), "r"(b1));
}

// chunk-major swizzled address (element granularity, returns byte offset)
__device__ __forceinline__ size_t cm_off(int tile, int kc, int nchunks, int row, int col /*fp16 col 0..63*/) {
    return (size_t)(tile * nchunks + kc) * TILEB + SW128((uint32_t)(row * 128 + col * 2));
}

// ============================================================================
// prep kernels (write chunk-major swizzled layouts directly)
// ============================================================================

// per-output-row abs-mean scale -> ternary pack (fp16, exact).
// For w_fc also append gate*u/scale columns (16) + zero pad (48) in chunk Kc-1.
__global__ void pack_w_kernel(const float* __restrict__ w, int K, int Kc,
                              __half* __restrict__ Bq,
                              float* __restrict__ scaleOut,
                              const float* __restrict__ u,
                              const float* __restrict__ gatep)
{
    int i = blockIdx.x;
    int t = threadIdx.x;  // 128 threads
    const float* wr = w + (size_t)i * K;
    double s = 0.0;
    for (int j = t; j < K; j += 128) s += fabs((double)wr[j]);
    for (int o = 16; o; o >>= 1) s += __shfl_down_sync(0xffffffffu, s, o);
    __shared__ double red[4];
    __shared__ float scsh;
    if ((t & 31) == 0) red[t >> 5] = s;
    __syncthreads();
    if (t == 0) {
        double tot = red[0] + red[1] + red[2] + red[3];
        float m = (float)(tot / K);
        scsh = fmaxf(m, 1e-5f);
        scaleOut[i] = scsh;
    }
    __syncthreads();
    float scale = scsh;
    char* base = (char*)Bq;
    int tile = i >> 7, row = i & 127;
    for (int j = t; j < K; j += 128) {
        float tern = rintf(wr[j] / scale);
        tern = fminf(fmaxf(tern, -1.f), 1.f);
        *(__half*)(base + cm_off(tile, j >> 6, Kc, row, j & 63)) = __float2half(tern);
    }
    if (u != nullptr && t < 64) {
        float g = *gatep;
        float val = (t < 16) ? g * u[(size_t)i * 16 + t] / scale : 0.f;
        *(__half*)(base + cm_off(tile, Kc - 1, Kc, row, t)) = __float2half(val);
    }
}

// W = fast_b @ v  (16 x 1024)
__global__ void compose_w_kernel(const float* __restrict__ fb, const float* __restrict__ v)
{
    int idx = blockIdx.x * blockDim.x + threadIdx.x;
    if (idx >= 16 * DIMD) return;
    int j = idx >> 10, d = idx & 1023;
    float s = 0.f;
#pragma unroll
    for (int r = 0; r < 16; r++) s += fb[j * 16 + r] * v[r * DIMD + d];
    g_W[idx] = s;
}

// fused: x row -> fp16 chunk-major (chunks 0..15) AND adapter t2 (chunk 16)
__global__ void prep_x_kernel(const float* __restrict__ x)
{
    __shared__ float xs[1024];
    int m = blockIdx.x;
    int tid = threadIdx.x;  // 128
    const float* xr = x + (size_t)m * DIMD;
    for (int i = tid; i < 1024; i += 128) xs[i] = xr[i];
    __syncthreads();
    int tile = m >> 7, row = m & 127;
    // fp16 conversion into chunks 0..15
    for (int i = tid; i < 512; i += 128) {
        int k = i * 2;
        __half2 h;
        h.x = __float2half(xs[k]);
        h.y = __float2half(xs[k + 1]);
        *(__half2*)((char*)g_A1 + cm_off(tile, k >> 6, KC1, row, k & 63)) = h;
    }
    // adapter t2
    int j = tid >> 3, p = tid & 7;
    const float* wr = g_W + j * 1024 + p * 128;
    const float* xp = xs + p * 128;
    float s = 0.f;
#pragma unroll 8
    for (int i = 0; i < 128; i++) s += xp[i] * wr[i];
#pragma unroll
    for (int o = 4; o; o >>= 1) s += __shfl_down_sync(0xffffffffu, s, o);
    if (p == 0)
        *(__half*)((char*)g_A1 + cm_off(tile, KC1 - 1, KC1, row, j)) = __float2half(s);
    if (tid < 48)
        *(__half*)((char*)g_A1 + cm_off(tile, KC1 - 1, KC1, row, 16 + tid)) = __float2half(0.f);
}

// ============================================================================
// GEMM: C[128,128] tile, fp16 HMMA f32-acc; 3-stage cp.async.bulk + mbarrier
// ring; 2 CTAs/SM (4 warps/SMSP) for latency hiding; single-buffered frags.
// EPI==1: h = scale_n*acc; r=relu(h); rr=r*r; write fp16(rr) chunk-major to g_R
// EPI==2: out = scale_n*acc (f32) row-major
// ============================================================================
#define BM 128
#define BN 128
#define NSTAGE 3
#define STAGEB 32768            // A 16KB + B 16KB
#define GEMM_SMEM (NSTAGE * STAGEB)

template <int EPI>
__global__ void __launch_bounds__(256, 2)
gemm_kernel(const __half* __restrict__ A, const __half* __restrict__ B,
            const float* __restrict__ scale, void* __restrict__ out,
            int kChunks, int nTiles)
{
    extern __shared__ char smem_raw[];
    __shared__ __align__(8) uint64_t mbar_store[2 * NSTAGE];
    __shared__ float s_scale[BN];
    const uint32_t DATA = smem_to_u32(smem_raw);
    const uint32_t FULL = smem_to_u32(mbar_store);
    const uint32_t EMPTY = FULL + 8 * NSTAGE;
    const int tid = (int)threadIdx.x;
    const int lane = tid & 31;
    const int wid = tid >> 5;
    const int wm = wid >> 2;          // 0..1 : 64-row slice of M
    const int wn = wid & 3;           // 0..3 : 32-col slice of N
    const int tile_m = (int)blockIdx.x / nTiles;
    const int tile_n = (int)blockIdx.x % nTiles;

    if (tid == 0) {
#pragma unroll
        for (int s = 0; s < NSTAGE; s++) {
            MBARRIER_INIT(FULL + 8 * s, 1);
            MBARRIER_INIT(EMPTY + 8 * s, 256);
        }
    }
    __syncthreads();

    const char* Ab = (const char*)A + (size_t)tile_m * kChunks * TILEB;
    const char* Bb = (const char*)B + (size_t)tile_n * kChunks * TILEB;

    auto produce = [&](int j) {
        int s = j % NSTAGE;
        uint32_t dst = DATA + s * STAGEB;
        MBARRIER_EXPECT_TX(FULL + 8 * s, 2 * TILEB);
        bulk_g2s(dst,         Ab + (size_t)j * TILEB, TILEB, FULL + 8 * s);
        bulk_g2s(dst + TILEB, Bb + (size_t)j * TILEB, TILEB, FULL + 8 * s);
    };

    if (tid == 0) {
        int npre = kChunks < NSTAGE ? kChunks : NSTAGE;
        for (int j = 0; j < npre; j++) produce(j);
    }

    float acc[16][4];
#pragma unroll
    for (int i = 0; i < 16; i++)
#pragma unroll
        for (int q = 0; q < 4; q++) acc[i][q] = 0.f;

    const int lr = lane & 15, lc = lane >> 4;
    uint32_t afr[4][4], bfr[2][4];

    for (int k = 0; k < kChunks; k++) {
        int s = k % NSTAGE;
        int ph = (k / NSTAGE) & 1;
        MBARRIER_WAIT_PARITY(FULL + 8 * s, ph);

        uint32_t sA = DATA + s * STAGEB;
        uint32_t sB = sA + TILEB;

#pragma unroll
        for (int ks = 0; ks < 4; ks++) {
            uint32_t bcol = (uint32_t)(ks * 32 + lc * 16);
#pragma unroll
            for (int im = 0; im < 4; im++) {
                int row = wm * 64 + im * 16 + lr;
                ldm_x4(sA + SW128((uint32_t)row * 128 + bcol), afr[im]);
            }
#pragma unroll
            for (int in2 = 0; in2 < 2; in2++) {
                int row = wn * 32 + in2 * 16 + lr;
                ldm_x4(sB + SW128((uint32_t)row * 128 + bcol), bfr[in2]);
            }
#pragma unroll
            for (int im = 0; im < 4; im++)
#pragma unroll
                for (int g = 0; g < 4; g++)
                    mma16816(acc[im * 4 + g], afr[im],
                             bfr[g >> 1][g & 1], bfr[g >> 1][(g & 1) + 2]);
        }
        // release this stage (our smem reads are done)
        MBARRIER_ARRIVE(EMPTY + 8 * s);
        if (tid == 0) {
            int j = k + NSTAGE;
            if (j < kChunks) {
                MBARRIER_WAIT_PARITY(EMPTY + 8 * s, ph);
                produce(j);
            }
        }
    }

    // ---- epilogue ----
    if (tid < BN) s_scale[tid] = scale[tile_n * BN + tid];
    __syncthreads();

#pragma unroll
    for (int im = 0; im < 4; im++) {
#pragma unroll
        for (int g = 0; g < 4; g++) {
            const float* c = acc[im * 4 + g];
            int ncol = wn * 32 + g * 8 + (lane & 3) * 2;
            int lrow0 = wm * 64 + im * 16 + (lane >> 2);
            float s0 = s_scale[ncol], s1 = s_scale[ncol + 1];
            if (EPI == 1) {
                int gcol = tile_n * BN + ncol;
                int kc = gcol >> 6, cc = gcol & 63;
#pragma unroll
                for (int half = 0; half < 2; half++) {
                    int lrow = lrow0 + half * 8;
                    float h0 = c[half * 2 + 0] * s0;
                    float h1 = c[half * 2 + 1] * s1;
                    float r0 = fmaxf(h0, 0.f), r1 = fmaxf(h1, 0.f);
                    __half2 hp;
                    hp.x = __float2half(r0 * r0);
                    hp.y = __float2half(r1 * r1);
                    *(__half2*)((char*)g_R + cm_off(tile_m, kc, KC2, lrow, cc)) = hp;
                }
            } else {
#pragma unroll
                for (int half = 0; half < 2; half++) {
                    int row = tile_m * BM + lrow0 + half * 8;
                    float2 v;
                    v.x = c[half * 2 + 0] * s0;
                    v.y = c[half * 2 + 1] * s1;
                    float* orow = (float*)out + (size_t)row * DIMD + tile_n * BN + ncol;
                    *(float2*)orow = v;
                }
            }
        }
    }
}

// ============================================================================
// launch
// ============================================================================
extern "C" void kernel_launch(void* const* d_in, const int* in_sizes, int n_in,
                              void* d_out, int out_size)
{
    const float* x      = (const float*)d_in[0];
    const float* fast_b = (const float*)d_in[1];
    const float* w_fc   = (const float*)d_in[2];
    const float* w_proj = (const float*)d_in[3];
    const float* u      = (const float*)d_in[4];
    const float* v      = (const float*)d_in[5];
    const float* gate   = (const float*)d_in[6];

    void *pA1, *pB1, *pR, *pB2, *pSfc, *pSpj;
    cudaGetSymbolAddress(&pA1, g_A1);
    cudaGetSymbolAddress(&pB1, g_B1);
    cudaGetSymbolAddress(&pR,  g_R);
    cudaGetSymbolAddress(&pB2, g_B2);
    cudaGetSymbolAddress(&pSfc, g_scale_fc);
    cudaGetSymbolAddress(&pSpj, g_scale_pj);

    cudaFuncSetAttribute(gemm_kernel<1>, cudaFuncAttributeMaxDynamicSharedMemorySize, GEMM_SMEM);
    cudaFuncSetAttribute(gemm_kernel<2>, cudaFuncAttributeMaxDynamicSharedMemorySize, GEMM_SMEM);

    // prep
    pack_w_kernel<<<HID, 128>>>(w_fc, DIMD, KC1, (__half*)pB1, (float*)pSfc, u, gate);
    pack_w_kernel<<<DIMD, 128>>>(w_proj, HID, KC2, (__half*)pB2, (float*)pSpj, nullptr, nullptr);
    compose_w_kernel<<<(16 * DIMD + 255) / 256, 256>>>(fast_b, v);
    prep_x_kernel<<<MTOK, 128>>>(x);

    // GEMM1: [16384 x 4096] = A1 @ B1^T  (+ relu^2), K = 17*64
    gemm_kernel<1><<<(MTOK / BM) * (HID / BN), 256, GEMM_SMEM>>>(
        (const __half*)pA1, (const __half*)pB1,
        (const float*)pSfc, pR, KC1, HID / BN);

    // GEMM2: out[16384 x 1024] = R @ B2^T, K = 64*64
    gemm_kernel<2><<<(MTOK / BM) * (DIMD / BN), 256, GEMM_SMEM>>>(
        (const __half*)pR, (const __half*)pB2,
        (const float*)pSpj, d_out, KC2, DIMD / BN);
}

// round 11
// speedup vs baseline: 6.4859x; 2.3552x over previous
#include <cuda_runtime.h>
#include <cuda_fp16.h>
#include <cstdint>
#include <cstddef>

// ---------------- problem dims (fixed for this problem) ----------------
#define DIMD 1024
#define HID  4096
#define MTOK 16384            // 4*4096 tokens
#define KC1  16               // GEMM1 k-chunks of 64 (adapter folded into weights)
#define KC2  64               // GEMM2 k-chunks of 64: 4096
#define TILEB 16384           // one 128x64 fp16 tile, SW128-swizzled

// Chunk-major tile layouts: buf[tileIdx][kchunk][128 rows][128B swizzled row]
// ---------------- device scratch (no cudaMalloc allowed) ----------------
__device__ __align__(1024) __half g_A1[(size_t)(MTOK / 128) * KC1 * TILEB / 2];
__device__ __align__(1024) __half g_B1[(size_t)(HID  / 128) * KC1 * TILEB / 2];
__device__ __align__(1024) __half g_R [(size_t)(MTOK / 128) * KC2 * TILEB / 2];
__device__ __align__(1024) __half g_B2[(size_t)(DIMD / 128) * KC2 * TILEB / 2];
__device__ float g_scale_fc[HID];
__device__ float g_scale_pj[DIMD];
__device__ float g_W[16 * DIMD];            // fast_b @ v           (16 x 1024)
__device__ float g_D[(size_t)HID * DIMD];   // gate * u @ W         (4096 x 1024)

// ---------------- helpers ----------------
__device__ __forceinline__ uint32_t smem_to_u32(const void* p) {
    uint32_t a;
    asm("{ .reg .u64 t; cvta.to.shared.u64 t, %1; cvt.u32.u64 %0, t; }" : "=r"(a) : "l"(p));
    return a;
}
#define SW128(o) ((o) ^ (((o) >> 3) & 0x70))

#define MBARRIER_INIT(mbar, count) \
    asm volatile("mbarrier.init.shared.b64 [%0], %1;" :: "r"((uint32_t)(mbar)), "r"((uint32_t)(count)) : "memory")
#define MBARRIER_EXPECT_TX(mbar, tx) \
    asm volatile("mbarrier.arrive.expect_tx.shared.b64 _, [%0], %1;" :: "r"((uint32_t)(mbar)), "r"((uint32_t)(tx)) : "memory")
#define MBARRIER_ARRIVE(mbar) \
    asm volatile("mbarrier.arrive.shared.b64 _, [%0];" :: "r"((uint32_t)(mbar)) : "memory")

#define MBARRIER_WAIT_PARITY(mbar, par) do { \
    uint32_t _m = (uint32_t)(mbar); uint32_t _p = (uint32_t)(par); uint32_t _d; \
    asm volatile("{\n\t.reg .pred p;\n\t" \
        "mbarrier.try_wait.parity.acquire.cta.shared::cta.b64 p, [%1], %2;\n\t" \
        "selp.b32 %0, 1, 0, p;\n\t}" : "=r"(_d) : "r"(_m), "r"(_p) : "memory"); \
    if (!_d) { \
        asm volatile("{\n\t.reg .pred P1;\n\t" \
            "WL_%=:\n\t" \
            "mbarrier.try_wait.parity.acquire.cta.shared::cta.b64 P1, [%0], %1, 0x989680;\n\t" \
            "@P1 bra.uni WD_%=;\n\tbra.uni WL_%=;\n\tWD_%=:\n\t}" \
            :: "r"(_m), "r"(_p) : "memory"); \
    } \
} while (0)

// bulk async copy GMEM -> SMEM with mbarrier complete_tx (base sm_90 ISA)
__device__ __forceinline__ void bulk_g2s(uint32_t dst, const void* src, uint32_t bytes, uint32_t mbar) {
    asm volatile("cp.async.bulk.shared::cluster.global.mbarrier::complete_tx::bytes [%0], [%1], %2, [%3];"
        :: "r"(dst), "l"(src), "r"(bytes), "r"(mbar) : "memory");
}

__device__ __forceinline__ void ldm_x4(uint32_t addr, uint32_t* r) {
    asm volatile("ldmatrix.sync.aligned.m8n8.x4.shared.b16 {%0,%1,%2,%3}, [%4];"
        : "=r"(r[0]), "=r"(r[1]), "=r"(r[2]), "=r"(r[3]) : "r"(addr));
}
__device__ __forceinline__ void mma16816(float* c, const uint32_t* a, uint32_t b0, uint32_t b1) {
    asm volatile("mma.sync.aligned.m16n8k16.row.col.f32.f16.f16.f32 "
        "{%0,%1,%2,%3}, {%4,%5,%6,%7}, {%8,%9}, {%0,%1,%2,%3};"
        : "+f"(c[0]), "+f"(c[1]), "+f"(c[2]), "+f"(c[3])
        : "r"(a[0]), "r"(a[1]), "r"(a[2]), "r"(a[3]), "r"(b0), "r"(b1));
}

// chunk-major swizzled address (element granularity, returns byte offset)
__device__ __forceinline__ size_t cm_off(int tile, int kc, int nchunks, int row, int col /*fp16 col 0..63*/) {
    return (size_t)(tile * nchunks + kc) * TILEB + SW128((uint32_t)(row * 128 + col * 2));
}

// ============================================================================
// prep kernels (write chunk-major swizzled layouts directly)
// ============================================================================

// W = fast_b @ v  (16 x 1024)
__global__ void compose_w_kernel(const float* __restrict__ fb, const float* __restrict__ v)
{
    int idx = blockIdx.x * blockDim.x + threadIdx.x;
    if (idx >= 16 * DIMD) return;
    int j = idx >> 10, d = idx & 1023;
    float s = 0.f;
#pragma unroll
    for (int r = 0; r < 16; r++) s += fb[j * 16 + r] * v[r * DIMD + d];
    g_W[idx] = s;
}

// D = gate * (u @ W)  (4096 x 1024); one block per output row
__global__ void compose_d_kernel(const float* __restrict__ u, const float* __restrict__ gatep)
{
    __shared__ float ur[16];
    int i = blockIdx.x;
    int tid = threadIdx.x;   // 256
    if (tid < 16) ur[tid] = u[(size_t)i * 16 + tid] * (*gatep);
    __syncthreads();
    float* drow = g_D + (size_t)i * DIMD;
#pragma unroll
    for (int q = 0; q < 4; q++) {
        int j = q * 256 + tid;
        float s = 0.f;
#pragma unroll
        for (int r = 0; r < 16; r++) s += ur[r] * g_W[r * DIMD + j];
        drow[j] = s;
    }
}

// per-output-row abs-mean scale -> ternary (+ optional adapter delta) fp16 pack.
__global__ void pack_w_kernel(const float* __restrict__ w, int K, int Kc,
                              __half* __restrict__ Bq,
                              float* __restrict__ scaleOut,
                              const float* __restrict__ D)
{
    int i = blockIdx.x;
    int t = threadIdx.x;  // 128 threads
    const float* wr = w + (size_t)i * K;
    double s = 0.0;
    for (int j = t; j < K; j += 128) s += fabs((double)wr[j]);
    for (int o = 16; o; o >>= 1) s += __shfl_down_sync(0xffffffffu, s, o);
    __shared__ double red[4];
    __shared__ float scsh;
    if ((t & 31) == 0) red[t >> 5] = s;
    __syncthreads();
    if (t == 0) {
        double tot = red[0] + red[1] + red[2] + red[3];
        float m = (float)(tot / K);
        scsh = fmaxf(m, 1e-5f);
        scaleOut[i] = scsh;
    }
    __syncthreads();
    float scale = scsh;
    float invs = 1.f / scale;
    char* base = (char*)Bq;
    int tile = i >> 7, row = i & 127;
    const float* drow = (D != nullptr) ? (D + (size_t)i * K) : nullptr;
    for (int j = t; j < K; j += 128) {
        float tern = rintf(wr[j] * invs);
        tern = fminf(fmaxf(tern, -1.f), 1.f);
        if (drow != nullptr) tern += drow[j] * invs;   // folded rank-16 adapter
        *(__half*)(base + cm_off(tile, j >> 6, Kc, row, j & 63)) = __float2half(tern);
    }
}

// x -> fp16 chunk-major A1 (16 chunks)
__global__ void prep_x_kernel(const float* __restrict__ x)
{
    size_t idx = (size_t)blockIdx.x * blockDim.x + threadIdx.x;   // pairs
    if (idx >= (size_t)MTOK * DIMD / 2) return;
    size_t m = idx / 512;
    int k = ((int)(idx % 512)) * 2;
    const float2 v = *(const float2*)(x + m * DIMD + k);
    __half2 h;
    h.x = __float2half(v.x);
    h.y = __float2half(v.y);
    *(__half2*)((char*)g_A1 + cm_off((int)(m >> 7), k >> 6, KC1, (int)(m & 127), k & 63)) = h;
}

// ============================================================================
// GEMM: C[128, BN] tile (BN = IM-dependent), fp16 HMMA f32-acc;
// cp.async.bulk + mbarrier ring; 2 CTAs/SM.
//   IM=4 -> BN=128 (warps 2x4, warptile 64x32)
//   IM=2 -> BN=64  (warps 4x2, warptile 32x32)
// B is ALWAYS packed in 128-row tiles; for BN=64 each 128-row tile holds
// SUBT=2 subtiles: subtile s is the contiguous 8KB half of each 16KB chunk
// (SW128 swizzle is self-contained per 8-row group, so halves are valid).
// EPI==1: h = scale_n*acc; r=relu(h); rr=r*r; fp16(rr) chunk-major to g_R
// EPI==2: out = scale_n*acc (f32) row-major
// ============================================================================
#define BM 128

template <int EPI, int IM, int NST>
__global__ void __launch_bounds__(256, 2)
gemm_kernel(const __half* __restrict__ A, const __half* __restrict__ B,
            const float* __restrict__ scale, void* __restrict__ out,
            int kChunks, int nTiles)
{
    constexpr int WN   = (IM == 4) ? 4 : 2;       // warps along N
    constexpr int BN   = WN * 32;                 // 128 or 64
    constexpr int BTB  = BN * 128;                // B tile bytes (16K or 8K)
    constexpr int SUBT = 128 / BN;                // subtiles per packed 128-row tile
    constexpr int STB  = TILEB + BTB;             // stage bytes

    extern __shared__ char smem_raw[];
    __shared__ __align__(8) uint64_t mbar_store[2 * NST];
    __shared__ float s_scale[BN];
    const uint32_t DATA = smem_to_u32(smem_raw);
    const uint32_t FULL = smem_to_u32(mbar_store);
    const uint32_t EMPTY = FULL + 8 * NST;
    const int tid = (int)threadIdx.x;
    const int lane = tid & 31;
    const int wid = tid >> 5;
    const int wm = wid / WN;                      // M-slice index
    const int wn = wid % WN;                      // N-slice index
    const int mbase = wm * (IM * 16);
    const int tile_m = (int)blockIdx.x / nTiles;
    const int tile_n = (int)blockIdx.x % nTiles;

    if (tid == 0) {
#pragma unroll
        for (int s = 0; s < NST; s++) {
            MBARRIER_INIT(FULL + 8 * s, 1);
            MBARRIER_INIT(EMPTY + 8 * s, 256);
        }
    }
    __syncthreads();

    const char* Ab = (const char*)A + (size_t)tile_m * kChunks * TILEB;
    // B addressing: 128-row packed tiles; pick the subtile's 8KB/16KB slice.
    const char* Bb = (const char*)B
        + (size_t)(tile_n / SUBT) * kChunks * TILEB
        + (size_t)(tile_n % SUBT) * BTB;

    auto produce = [&](int j) {
        int s = j % NST;
        uint32_t dst = DATA + s * STB;
        MBARRIER_EXPECT_TX(FULL + 8 * s, (uint32_t)STB);
        bulk_g2s(dst,         Ab + (size_t)j * TILEB, TILEB, FULL + 8 * s);
        bulk_g2s(dst + TILEB, Bb + (size_t)j * TILEB, BTB,   FULL + 8 * s);
    };

    if (tid == 0) {
        int npre = kChunks < NST ? kChunks : NST;
        for (int j = 0; j < npre; j++) produce(j);
    }

    float acc[IM * 4][4];
#pragma unroll
    for (int i = 0; i < IM * 4; i++)
#pragma unroll
        for (int q = 0; q < 4; q++) acc[i][q] = 0.f;

    const int lr = lane & 15, lc = lane >> 4;
    uint32_t afr[IM][4], bfr[2][4];

    for (int k = 0; k < kChunks; k++) {
        int s = k % NST;
        int ph = (k / NST) & 1;
        MBARRIER_WAIT_PARITY(FULL + 8 * s, ph);

        uint32_t sA = DATA + s * STB;
        uint32_t sB = sA + TILEB;

#pragma unroll
        for (int ks = 0; ks < 4; ks++) {
            uint32_t bcol = (uint32_t)(ks * 32 + lc * 16);
#pragma unroll
            for (int im = 0; im < IM; im++) {
                int row = mbase + im * 16 + lr;
                ldm_x4(sA + SW128((uint32_t)row * 128 + bcol), afr[im]);
            }
#pragma unroll
            for (int in2 = 0; in2 < 2; in2++) {
                int row = wn * 32 + in2 * 16 + lr;
                ldm_x4(sB + SW128((uint32_t)row * 128 + bcol), bfr[in2]);
            }
#pragma unroll
            for (int im = 0; im < IM; im++)
#pragma unroll
                for (int g = 0; g < 4; g++)
                    mma16816(acc[im * 4 + g], afr[im],
                             bfr[g >> 1][g & 1], bfr[g >> 1][(g & 1) + 2]);
        }
        // release this stage (our smem reads are done)
        MBARRIER_ARRIVE(EMPTY + 8 * s);
        if (tid == 0) {
            int j = k + NST;
            if (j < kChunks) {
                MBARRIER_WAIT_PARITY(EMPTY + 8 * s, ph);
                produce(j);
            }
        }
    }

    // ---- epilogue ----
    if (tid < BN) s_scale[tid] = scale[tile_n * BN + tid];
    __syncthreads();

#pragma unroll
    for (int im = 0; im < IM; im++) {
#pragma unroll
        for (int g = 0; g < 4; g++) {
            const float* c = acc[im * 4 + g];
            int ncol = wn * 32 + g * 8 + (lane & 3) * 2;
            int lrow0 = mbase + im * 16 + (lane >> 2);
            float s0 = s_scale[ncol], s1 = s_scale[ncol + 1];
            if (EPI == 1) {
                int gcol = tile_n * BN + ncol;
                int kc = gcol >> 6, cc = gcol & 63;
#pragma unroll
                for (int half = 0; half < 2; half++) {
                    int lrow = lrow0 + half * 8;
                    float h0 = c[half * 2 + 0] * s0;
                    float h1 = c[half * 2 + 1] * s1;
                    float r0 = fmaxf(h0, 0.f), r1 = fmaxf(h1, 0.f);
                    __half2 hp;
                    hp.x = __float2half(r0 * r0);
                    hp.y = __float2half(r1 * r1);
                    *(__half2*)((char*)g_R + cm_off(tile_m, kc, KC2, lrow, cc)) = hp;
                }
            } else {
#pragma unroll
                for (int half = 0; half < 2; half++) {
                    int row = tile_m * BM + lrow0 + half * 8;
                    float2 v;
                    v.x = c[half * 2 + 0] * s0;
                    v.y = c[half * 2 + 1] * s1;
                    float* orow = (float*)out + (size_t)row * DIMD + tile_n * BN + ncol;
                    *(float2*)orow = v;
                }
            }
        }
    }
}

// ============================================================================
// launch
// ============================================================================
extern "C" void kernel_launch(void* const* d_in, const int* in_sizes, int n_in,
                              void* d_out, int out_size)
{
    const float* x      = (const float*)d_in[0];
    const float* fast_b = (const float*)d_in[1];
    const float* w_fc   = (const float*)d_in[2];
    const float* w_proj = (const float*)d_in[3];
    const float* u      = (const float*)d_in[4];
    const float* v      = (const float*)d_in[5];
    const float* gate   = (const float*)d_in[6];

    void *pA1, *pB1, *pR, *pB2, *pSfc, *pSpj, *pD;
    cudaGetSymbolAddress(&pA1, g_A1);
    cudaGetSymbolAddress(&pB1, g_B1);
    cudaGetSymbolAddress(&pR,  g_R);
    cudaGetSymbolAddress(&pB2, g_B2);
    cudaGetSymbolAddress(&pSfc, g_scale_fc);
    cudaGetSymbolAddress(&pSpj, g_scale_pj);
    cudaGetSymbolAddress(&pD, g_D);

    // GEMM1: 128x128 tiles, 3 stages (32KB/stage) -> 96KB, 2 CTAs/SM
    constexpr int SMEM1 = 3 * (TILEB + 128 * 128);
    // GEMM2: 128x64 tiles, 4 stages (24KB/stage) -> 96KB, 2 CTAs/SM
    constexpr int SMEM2 = 4 * (TILEB + 64 * 128);
    cudaFuncSetAttribute((const void*)gemm_kernel<1, 4, 3>, cudaFuncAttributeMaxDynamicSharedMemorySize, SMEM1);
    cudaFuncSetAttribute((const void*)gemm_kernel<2, 2, 4>, cudaFuncAttributeMaxDynamicSharedMemorySize, SMEM2);

    // prep
    compose_w_kernel<<<(16 * DIMD + 255) / 256, 256>>>(fast_b, v);
    compose_d_kernel<<<HID, 256>>>(u, gate);
    pack_w_kernel<<<HID, 128>>>(w_fc, DIMD, KC1, (__half*)pB1, (float*)pSfc, (const float*)pD);
    pack_w_kernel<<<DIMD, 128>>>(w_proj, HID, KC2, (__half*)pB2, (float*)pSpj, nullptr);
    prep_x_kernel<<<(MTOK * DIMD / 2 + 255) / 256, 256>>>(x);

    // GEMM1: [16384 x 4096] = A1 @ B1^T  (+ relu^2), K = 16*64, BN=128
    gemm_kernel<1, 4, 3><<<(MTOK / BM) * (HID / 128), 256, SMEM1>>>(
        (const __half*)pA1, (const __half*)pB1,
        (const float*)pSfc, pR, KC1, HID / 128);

    // GEMM2: out[16384 x 1024] = R @ B2^T, K = 64*64, BN=64
    gemm_kernel<2, 2, 4><<<(MTOK / BM) * (DIMD / 64), 256, SMEM2>>>(
        (const __half*)pR, (const __half*)pB2,
        (const float*)pSpj, d_out, KC2, DIMD / 64);
}